// round 1
// baseline (speedup 1.0000x reference)
#include <cuda_runtime.h>

#define SEQ 262144
#define HID 256
// 2 * log2(e): folds the tanh argument scaling into precomputed terms
#define KLOG2E 2.8853900817779268f

// Scratch: precomputed K*(B@u_t + bA), padded for prefetch overrun
__device__ float4 g_wbuf[SEQ + 32];

__device__ __forceinline__ float ex2_approx(float x) {
    float y; asm("ex2.approx.f32 %0, %1;" : "=f"(y) : "f"(x)); return y;
}
__device__ __forceinline__ float rcp_approx(float x) {
    float y; asm("rcp.approx.f32 %0, %1;" : "=f"(y) : "f"(x)); return y;
}

// ---------------------------------------------------------------------------
// Pass 1 (parallel): w_t = K * (B @ u_t + bA)   [K = 2*log2e]
// ---------------------------------------------------------------------------
__global__ void prep_kernel(const float* __restrict__ u,
                            const float* __restrict__ B,
                            const float* __restrict__ bA) {
    int t = blockIdx.x * blockDim.x + threadIdx.x;
    if (t >= SEQ) return;
    float b00 = __ldg(B + 0), b01 = __ldg(B + 1), b02 = __ldg(B + 2);
    float b10 = __ldg(B + 3), b11 = __ldg(B + 4), b12 = __ldg(B + 5);
    float b20 = __ldg(B + 6), b21 = __ldg(B + 7), b22 = __ldg(B + 8);
    float a0 = __ldg(bA + 0), a1 = __ldg(bA + 1), a2 = __ldg(bA + 2);

    float u0 = u[t], u1 = u[SEQ + t], u2 = u[2 * SEQ + t];

    float w0 = KLOG2E * fmaf(b00, u0, fmaf(b01, u1, fmaf(b02, u2, a0)));
    float w1 = KLOG2E * fmaf(b10, u0, fmaf(b11, u1, fmaf(b12, u2, a1)));
    float w2 = KLOG2E * fmaf(b20, u0, fmaf(b21, u1, fmaf(b22, u2, a2)));
    g_wbuf[t] = make_float4(w0, w1, w2, 0.0f);
}

// ---------------------------------------------------------------------------
// Pass 2 (serial latency chain): x_{t+1} = x_t + dt * tanh(A x_t + (Bu_t+bA))
// tanh(y) = 1 - 2/(exp(2y)+1) = 1 - 2*rcp(ex2(K*y)+1); K folded into A and w.
// Single thread; double-buffered prefetch of w; vectorized membrane stores.
// ---------------------------------------------------------------------------
__global__ void scan_kernel(const float* __restrict__ A,
                            const float* __restrict__ dtp,
                            float* __restrict__ memb) {
    if (threadIdx.x != 0) return;

    float dt   = *dtp;
    float m2dt = -2.0f * dt;
    float a00 = KLOG2E * A[0], a01 = KLOG2E * A[1], a02 = KLOG2E * A[2];
    float a10 = KLOG2E * A[3], a11 = KLOG2E * A[4], a12 = KLOG2E * A[5];
    float a20 = KLOG2E * A[6], a21 = KLOG2E * A[7], a22 = KLOG2E * A[8];

    float x0 = 0.0f, x1 = 0.0f, x2 = 0.0f;

    float4 wa[8], wb[8];
#pragma unroll
    for (int i = 0; i < 8; i++) wa[i] = g_wbuf[i];

    float s0[8], s1[8], s2[8];

#define STEP(WV)                                                               \
    do {                                                                       \
        float xp0 = x0 + dt, xp1 = x1 + dt, xp2 = x2 + dt;                     \
        float p0 = fmaf(a00, x0, fmaf(a01, x1, fmaf(a02, x2, (WV).x)));        \
        float p1 = fmaf(a10, x0, fmaf(a11, x1, fmaf(a12, x2, (WV).y)));        \
        float p2 = fmaf(a20, x0, fmaf(a21, x1, fmaf(a22, x2, (WV).z)));        \
        float r0 = rcp_approx(ex2_approx(p0) + 1.0f);                          \
        float r1 = rcp_approx(ex2_approx(p1) + 1.0f);                          \
        float r2 = rcp_approx(ex2_approx(p2) + 1.0f);                          \
        x0 = fmaf(m2dt, r0, xp0);                                              \
        x1 = fmaf(m2dt, r1, xp1);                                              \
        x2 = fmaf(m2dt, r2, xp2);                                              \
    } while (0)

#define FLUSH(BASE)                                                            \
    do {                                                                       \
        *(float4*)(memb + 0 * SEQ + (BASE))     = make_float4(s0[0], s0[1], s0[2], s0[3]); \
        *(float4*)(memb + 0 * SEQ + (BASE) + 4) = make_float4(s0[4], s0[5], s0[6], s0[7]); \
        *(float4*)(memb + 1 * SEQ + (BASE))     = make_float4(s1[0], s1[1], s1[2], s1[3]); \
        *(float4*)(memb + 1 * SEQ + (BASE) + 4) = make_float4(s1[4], s1[5], s1[6], s1[7]); \
        *(float4*)(memb + 2 * SEQ + (BASE))     = make_float4(s2[0], s2[1], s2[2], s2[3]); \
        *(float4*)(memb + 2 * SEQ + (BASE) + 4) = make_float4(s2[4], s2[5], s2[6], s2[7]); \
    } while (0)

    for (int base = 0; base < SEQ; base += 16) {
        // prefetch next 8 while processing current 8 (loads are off the chain)
#pragma unroll
        for (int i = 0; i < 8; i++) wb[i] = g_wbuf[base + 8 + i];
#pragma unroll
        for (int k = 0; k < 8; k++) {
            STEP(wa[k]);
            s0[k] = x0; s1[k] = x1; s2[k] = x2;
        }
        FLUSH(base);
#pragma unroll
        for (int i = 0; i < 8; i++) wa[i] = g_wbuf[base + 16 + i];
#pragma unroll
        for (int k = 0; k < 8; k++) {
            STEP(wb[k]);
            s0[k] = x0; s1[k] = x1; s2[k] = x2;
        }
        FLUSH(base + 8);
    }
#undef STEP
#undef FLUSH
}

// ---------------------------------------------------------------------------
// Pass 3 (parallel): out = W2 @ relu(W1 @ x + b1) + b2, per timestep.
// Weights staged in smem (broadcast reads); 4 timesteps per thread for
// LDS amortization. Grid = SEQ/1024 blocks of 256 threads.
// ---------------------------------------------------------------------------
__global__ void mlp_kernel(const float* __restrict__ W1, const float* __restrict__ b1,
                           const float* __restrict__ W2, const float* __restrict__ b2,
                           const float* __restrict__ memb, float* __restrict__ out) {
    __shared__ float sW1[HID * 3];
    __shared__ float sb1[HID];
    __shared__ float sW2[3 * HID];
    __shared__ float sb2[3];

    int tid = threadIdx.x;
    for (int i = tid; i < HID * 3; i += 256) { sW1[i] = W1[i]; sW2[i] = W2[i]; }
    if (tid < HID) sb1[tid] = b1[tid];
    if (tid < 3)   sb2[tid] = b2[tid];
    __syncthreads();

    int t0 = blockIdx.x * 1024 + tid;

    float X0[4], X1[4], X2[4], Ac0[4], Ac1[4], Ac2[4];
#pragma unroll
    for (int k = 0; k < 4; k++) {
        int t = t0 + k * 256;
        X0[k] = memb[t];
        X1[k] = memb[SEQ + t];
        X2[k] = memb[2 * SEQ + t];
        Ac0[k] = sb2[0]; Ac1[k] = sb2[1]; Ac2[k] = sb2[2];
    }

#pragma unroll 8
    for (int h = 0; h < HID; h++) {
        float w0 = sW1[3 * h], w1 = sW1[3 * h + 1], w2 = sW1[3 * h + 2];
        float bb = sb1[h];
        float v0 = sW2[h], v1 = sW2[HID + h], v2 = sW2[2 * HID + h];
#pragma unroll
        for (int k = 0; k < 4; k++) {
            float hv = fmaf(w0, X0[k], fmaf(w1, X1[k], fmaf(w2, X2[k], bb)));
            hv = fmaxf(hv, 0.0f);
            Ac0[k] = fmaf(v0, hv, Ac0[k]);
            Ac1[k] = fmaf(v1, hv, Ac1[k]);
            Ac2[k] = fmaf(v2, hv, Ac2[k]);
        }
    }

#pragma unroll
    for (int k = 0; k < 4; k++) {
        int t = t0 + k * 256;
        out[t]           = Ac0[k];
        out[SEQ + t]     = Ac1[k];
        out[2 * SEQ + t] = Ac2[k];
    }
}

// ---------------------------------------------------------------------------
// Inputs (metadata order): u, dt, A, B, bA, W1, b1, W2, b2
// Output: [outputs (3*SEQ) | membranes (3*SEQ)]
// ---------------------------------------------------------------------------
extern "C" void kernel_launch(void* const* d_in, const int* in_sizes, int n_in,
                              void* d_out, int out_size) {
    const float* u  = (const float*)d_in[0];
    const float* dt = (const float*)d_in[1];
    const float* A  = (const float*)d_in[2];
    const float* B  = (const float*)d_in[3];
    const float* bA = (const float*)d_in[4];
    const float* W1 = (const float*)d_in[5];
    const float* b1 = (const float*)d_in[6];
    const float* W2 = (const float*)d_in[7];
    const float* b2 = (const float*)d_in[8];
    float* out  = (float*)d_out;
    float* memb = out + 3 * SEQ;

    prep_kernel<<<SEQ / 256, 256>>>(u, B, bA);
    scan_kernel<<<1, 32>>>(A, dt, memb);
    mlp_kernel<<<SEQ / 1024, 256>>>(W1, b1, W2, b2, memb, out);
}

// round 2
// speedup vs baseline: 1.2015x; 1.2015x over previous
#include <cuda_runtime.h>

#define SEQ 262144
#define HID 256
// 2 * log2(e): folds the tanh argument scaling into precomputed terms
#define KLOG2E 2.8853900817779268f

// scan chunking: producer emits CH steps, flushers drain them (lag-2 backpressure)
#define CH 512
#define NCH (SEQ / CH)
#define RING 1024          // entries (2 chunks), float4 each -> 16KB smem
#define RMASK (RING - 1)

// Scratch: precomputed K*(B@u_t + bA), padded for prefetch overrun
__device__ float4 g_wbuf[SEQ + 64];

__device__ __forceinline__ float ex2_approx(float x) {
    float y; asm("ex2.approx.f32 %0, %1;" : "=f"(y) : "f"(x)); return y;
}
__device__ __forceinline__ float rcp_approx(float x) {
    float y; asm("rcp.approx.f32 %0, %1;" : "=f"(y) : "f"(x)); return y;
}

// ---------------------------------------------------------------------------
// Pass 1 (parallel): w_t = K * (B @ u_t + bA)   [K = 2*log2e]
// ---------------------------------------------------------------------------
__global__ void prep_kernel(const float* __restrict__ u,
                            const float* __restrict__ B,
                            const float* __restrict__ bA) {
    int t = blockIdx.x * blockDim.x + threadIdx.x;
    if (t >= SEQ) return;
    float b00 = __ldg(B + 0), b01 = __ldg(B + 1), b02 = __ldg(B + 2);
    float b10 = __ldg(B + 3), b11 = __ldg(B + 4), b12 = __ldg(B + 5);
    float b20 = __ldg(B + 6), b21 = __ldg(B + 7), b22 = __ldg(B + 8);
    float a0 = __ldg(bA + 0), a1 = __ldg(bA + 1), a2 = __ldg(bA + 2);

    float u0 = u[t], u1 = u[SEQ + t], u2 = u[2 * SEQ + t];

    float w0 = KLOG2E * fmaf(b00, u0, fmaf(b01, u1, fmaf(b02, u2, a0)));
    float w1 = KLOG2E * fmaf(b10, u0, fmaf(b11, u1, fmaf(b12, u2, a1)));
    float w2 = KLOG2E * fmaf(b20, u0, fmaf(b21, u1, fmaf(b22, u2, a2)));
    g_wbuf[t] = make_float4(w0, w1, w2, 0.0f);
}

// ---------------------------------------------------------------------------
// Pass 2: warp-specialized serial scan.
//   warp 0 / lane 0 : recurrence, STS.128 of x into smem ring (issue-only)
//   warps 1-3 (96t) : drain ring -> 3 coalesced global planes (STG.32)
// Named barriers: bar1 = "chunk ready" (producer arrives, flushers sync)
//                 bar2 = "chunk flushed" (flushers arrive, producer syncs, lag 2)
// tanh(y) = 1 - 2*rcp(ex2(K*y)+1); K folded into A (here) and w (prep).
// ---------------------------------------------------------------------------
__global__ void __launch_bounds__(128, 1)
scan_kernel(const float* __restrict__ A,
            const float* __restrict__ dtp,
            float* __restrict__ memb) {
    __shared__ float4 ring[RING];

    int tid = threadIdx.x;

    if (tid < 32) {
        // ---------------- producer warp ----------------
        float dt   = *dtp;
        float m2dt = -2.0f * dt;
        float a00 = KLOG2E * A[0], a01 = KLOG2E * A[1], a02 = KLOG2E * A[2];
        float a10 = KLOG2E * A[3], a11 = KLOG2E * A[4], a12 = KLOG2E * A[5];
        float a20 = KLOG2E * A[6], a21 = KLOG2E * A[7], a22 = KLOG2E * A[8];

        float x0 = 0.0f, x1 = 0.0f, x2 = 0.0f;
        float4 wa[8], wb[8];
        if (tid == 0) {
#pragma unroll
            for (int i = 0; i < 8; i++) wa[i] = g_wbuf[i];
        }

#define STEP(WV)                                                               \
    do {                                                                       \
        float xp0 = x0 + dt, xp1 = x1 + dt, xp2 = x2 + dt;                     \
        float p0 = fmaf(a00, x0, fmaf(a01, x1, fmaf(a02, x2, (WV).x)));        \
        float p1 = fmaf(a10, x0, fmaf(a11, x1, fmaf(a12, x2, (WV).y)));        \
        float p2 = fmaf(a20, x0, fmaf(a21, x1, fmaf(a22, x2, (WV).z)));        \
        float r0 = rcp_approx(ex2_approx(p0) + 1.0f);                          \
        float r1 = rcp_approx(ex2_approx(p1) + 1.0f);                          \
        float r2 = rcp_approx(ex2_approx(p2) + 1.0f);                          \
        x0 = fmaf(m2dt, r0, xp0);                                              \
        x1 = fmaf(m2dt, r1, xp1);                                              \
        x2 = fmaf(m2dt, r2, xp2);                                              \
    } while (0)

        for (int c = 0; c < NCH; c++) {
            if (c >= 2)  // wait until chunk c-2 is flushed (ring slot reuse safe)
                asm volatile("bar.sync 2, 128;" ::: "memory");

            if (tid == 0) {
                int base = c * CH;
                for (int b = base; b < base + CH; b += 16) {
                    int ri = b & RMASK;
#pragma unroll
                    for (int i = 0; i < 8; i++) wb[i] = g_wbuf[b + 8 + i];
#pragma unroll
                    for (int k = 0; k < 8; k++) {
                        STEP(wa[k]);
                        ring[ri + k] = make_float4(x0, x1, x2, 0.0f);
                    }
#pragma unroll
                    for (int i = 0; i < 8; i++) wa[i] = g_wbuf[b + 16 + i];
#pragma unroll
                    for (int k = 0; k < 8; k++) {
                        STEP(wb[k]);
                        ring[ri + 8 + k] = make_float4(x0, x1, x2, 0.0f);
                    }
                }
                // make ring writes visible to flusher warps before signaling
                asm volatile("membar.cta;" ::: "memory");
            }
            __syncwarp();
            asm volatile("bar.arrive 1, 128;" ::: "memory");  // chunk c ready
        }
#undef STEP
    } else {
        // ---------------- flusher warps (96 threads) ----------------
        int ft = tid - 32;
        for (int c = 0; c < NCH; c++) {
            asm volatile("bar.sync 1, 128;" ::: "memory");  // chunk c ready
            int base = c * CH;
#pragma unroll 2
            for (int s = ft; s < CH; s += 96) {
                float4 v = ring[(base + s) & RMASK];
                int t = base + s;
                memb[t]           = v.x;
                memb[SEQ + t]     = v.y;
                memb[2 * SEQ + t] = v.z;
            }
            asm volatile("bar.arrive 2, 128;" ::: "memory");  // chunk c flushed
        }
    }
}

// ---------------------------------------------------------------------------
// Pass 3 (parallel): out = W2 @ relu(W1 @ x + b1) + b2, per timestep.
// ---------------------------------------------------------------------------
__global__ void mlp_kernel(const float* __restrict__ W1, const float* __restrict__ b1,
                           const float* __restrict__ W2, const float* __restrict__ b2,
                           const float* __restrict__ memb, float* __restrict__ out) {
    __shared__ float sW1[HID * 3];
    __shared__ float sb1[HID];
    __shared__ float sW2[3 * HID];
    __shared__ float sb2[3];

    int tid = threadIdx.x;
    for (int i = tid; i < HID * 3; i += 256) { sW1[i] = W1[i]; sW2[i] = W2[i]; }
    if (tid < HID) sb1[tid] = b1[tid];
    if (tid < 3)   sb2[tid] = b2[tid];
    __syncthreads();

    int t0 = blockIdx.x * 1024 + tid;

    float X0[4], X1[4], X2[4], Ac0[4], Ac1[4], Ac2[4];
#pragma unroll
    for (int k = 0; k < 4; k++) {
        int t = t0 + k * 256;
        X0[k] = memb[t];
        X1[k] = memb[SEQ + t];
        X2[k] = memb[2 * SEQ + t];
        Ac0[k] = sb2[0]; Ac1[k] = sb2[1]; Ac2[k] = sb2[2];
    }

#pragma unroll 8
    for (int h = 0; h < HID; h++) {
        float w0 = sW1[3 * h], w1 = sW1[3 * h + 1], w2 = sW1[3 * h + 2];
        float bb = sb1[h];
        float v0 = sW2[h], v1 = sW2[HID + h], v2 = sW2[2 * HID + h];
#pragma unroll
        for (int k = 0; k < 4; k++) {
            float hv = fmaf(w0, X0[k], fmaf(w1, X1[k], fmaf(w2, X2[k], bb)));
            hv = fmaxf(hv, 0.0f);
            Ac0[k] = fmaf(v0, hv, Ac0[k]);
            Ac1[k] = fmaf(v1, hv, Ac1[k]);
            Ac2[k] = fmaf(v2, hv, Ac2[k]);
        }
    }

#pragma unroll
    for (int k = 0; k < 4; k++) {
        int t = t0 + k * 256;
        out[t]           = Ac0[k];
        out[SEQ + t]     = Ac1[k];
        out[2 * SEQ + t] = Ac2[k];
    }
}

// ---------------------------------------------------------------------------
// Inputs (metadata order): u, dt, A, B, bA, W1, b1, W2, b2
// Output: [outputs (3*SEQ) | membranes (3*SEQ)]
// ---------------------------------------------------------------------------
extern "C" void kernel_launch(void* const* d_in, const int* in_sizes, int n_in,
                              void* d_out, int out_size) {
    const float* u  = (const float*)d_in[0];
    const float* dt = (const float*)d_in[1];
    const float* A  = (const float*)d_in[2];
    const float* B  = (const float*)d_in[3];
    const float* bA = (const float*)d_in[4];
    const float* W1 = (const float*)d_in[5];
    const float* b1 = (const float*)d_in[6];
    const float* W2 = (const float*)d_in[7];
    const float* b2 = (const float*)d_in[8];
    float* out  = (float*)d_out;
    float* memb = out + 3 * SEQ;

    prep_kernel<<<SEQ / 256, 256>>>(u, B, bA);
    scan_kernel<<<1, 128>>>(A, dt, memb);
    mlp_kernel<<<SEQ / 1024, 256>>>(W1, b1, W2, b2, memb, out);
}

// round 3
// speedup vs baseline: 2.0581x; 1.7130x over previous
#include <cuda_runtime.h>

#define SEQ 262144
#define HID 256

// scan chunking: producer emits CH steps, flushers drain them (lag-2 backpressure)
#define CH 512
#define NCH (SEQ / CH)
#define RING 1024          // entries (2 chunks), float4 each -> 16KB smem
#define RMASK (RING - 1)

// Scratch: precomputed w_t = B@u_t + bA, padded for prefetch overrun
__device__ float4 g_wbuf[SEQ + 64];

__device__ __forceinline__ float tanh_approx(float x) {
    float y; asm("tanh.approx.f32 %0, %1;" : "=f"(y) : "f"(x)); return y;
}

// ---------------------------------------------------------------------------
// Pass 1 (parallel): w_t = B @ u_t + bA
// ---------------------------------------------------------------------------
__global__ void prep_kernel(const float* __restrict__ u,
                            const float* __restrict__ B,
                            const float* __restrict__ bA) {
    int t = blockIdx.x * blockDim.x + threadIdx.x;
    if (t >= SEQ) return;
    float b00 = __ldg(B + 0), b01 = __ldg(B + 1), b02 = __ldg(B + 2);
    float b10 = __ldg(B + 3), b11 = __ldg(B + 4), b12 = __ldg(B + 5);
    float b20 = __ldg(B + 6), b21 = __ldg(B + 7), b22 = __ldg(B + 8);
    float a0 = __ldg(bA + 0), a1 = __ldg(bA + 1), a2 = __ldg(bA + 2);

    float u0 = u[t], u1 = u[SEQ + t], u2 = u[2 * SEQ + t];

    float w0 = fmaf(b00, u0, fmaf(b01, u1, fmaf(b02, u2, a0)));
    float w1 = fmaf(b10, u0, fmaf(b11, u1, fmaf(b12, u2, a1)));
    float w2 = fmaf(b20, u0, fmaf(b21, u1, fmaf(b22, u2, a2)));
    g_wbuf[t] = make_float4(w0, w1, w2, 0.0f);
}

// ---------------------------------------------------------------------------
// Pass 2: warp-specialized serial scan, y-domain recurrence.
//   y_t = A x_t + w_t ;  th_t = tanh(y_t)
//   x_{t+1} = x_t + dt*th_t                       (off the critical chain)
//   y_{t+1} = y_t + (w_{t+1}-w_t) + (dt*A)*th_t   (critical chain: tanh + 3 FFMA)
//   warp 0 / lane 0 : recurrence, STS.128 of x into smem ring
//   warps 1-3 (96t) : drain ring -> 3 coalesced global planes
// ---------------------------------------------------------------------------
__global__ void __launch_bounds__(128, 1)
scan_kernel(const float* __restrict__ A,
            const float* __restrict__ dtp,
            float* __restrict__ memb) {
    __shared__ float4 ring[RING];

    int tid = threadIdx.x;

    if (tid < 32) {
        // ---------------- producer warp ----------------
        float dt = *dtp;
        // d = dt * A
        float d00 = dt * A[0], d01 = dt * A[1], d02 = dt * A[2];
        float d10 = dt * A[3], d11 = dt * A[4], d12 = dt * A[5];
        float d20 = dt * A[6], d21 = dt * A[7], d22 = dt * A[8];

        float x0 = 0.0f, x1 = 0.0f, x2 = 0.0f;
        float y0 = 0.0f, y1 = 0.0f, y2 = 0.0f;

        float4 wa[8], wb[8];
        if (tid == 0) {
#pragma unroll
            for (int i = 0; i < 8; i++) wa[i] = g_wbuf[i];
            y0 = wa[0].x; y1 = wa[0].y; y2 = wa[0].z;   // y_0 = w_0 (x_0 = 0)
        }

        // Chain: tanh(y) -> 3 chained FFMA (earliest-ready th innermost) -> y'
#define STEP(W, WN)                                                            \
    do {                                                                       \
        float th0 = tanh_approx(y0);                                           \
        float th1 = tanh_approx(y1);                                           \
        float th2 = tanh_approx(y2);                                           \
        float q0 = y0 + ((WN).x - (W).x);                                      \
        float q1 = y1 + ((WN).y - (W).y);                                      \
        float q2 = y2 + ((WN).z - (W).z);                                      \
        x0 = fmaf(dt, th0, x0);                                                \
        x1 = fmaf(dt, th1, x1);                                                \
        x2 = fmaf(dt, th2, x2);                                                \
        y0 = fmaf(d02, th2, fmaf(d01, th1, fmaf(d00, th0, q0)));               \
        y1 = fmaf(d12, th2, fmaf(d11, th1, fmaf(d10, th0, q1)));               \
        y2 = fmaf(d22, th2, fmaf(d21, th1, fmaf(d20, th0, q2)));               \
    } while (0)

        for (int c = 0; c < NCH; c++) {
            if (c >= 2)  // wait until chunk c-2 is flushed (ring slot reuse safe)
                asm volatile("bar.sync 2, 128;" ::: "memory");

            if (tid == 0) {
                int base = c * CH;
                for (int b = base; b < base + CH; b += 16) {
                    int ri = b & RMASK;
#pragma unroll
                    for (int i = 0; i < 8; i++) wb[i] = g_wbuf[b + 8 + i];
#pragma unroll
                    for (int k = 0; k < 8; k++) {
                        STEP(wa[k], (k < 7 ? wa[k + 1] : wb[0]));
                        ring[ri + k] = make_float4(x0, x1, x2, 0.0f);
                    }
#pragma unroll
                    for (int i = 0; i < 8; i++) wa[i] = g_wbuf[b + 16 + i];
#pragma unroll
                    for (int k = 0; k < 8; k++) {
                        STEP(wb[k], (k < 7 ? wb[k + 1] : wa[0]));
                        ring[ri + 8 + k] = make_float4(x0, x1, x2, 0.0f);
                    }
                }
                // make ring writes visible to flusher warps before signaling
                asm volatile("membar.cta;" ::: "memory");
            }
            __syncwarp();
            asm volatile("bar.arrive 1, 128;" ::: "memory");  // chunk c ready
        }
#undef STEP
    } else {
        // ---------------- flusher warps (96 threads) ----------------
        int ft = tid - 32;
        for (int c = 0; c < NCH; c++) {
            asm volatile("bar.sync 1, 128;" ::: "memory");  // chunk c ready
            int base = c * CH;
#pragma unroll 2
            for (int s = ft; s < CH; s += 96) {
                float4 v = ring[(base + s) & RMASK];
                int t = base + s;
                memb[t]           = v.x;
                memb[SEQ + t]     = v.y;
                memb[2 * SEQ + t] = v.z;
            }
            asm volatile("bar.arrive 2, 128;" ::: "memory");  // chunk c flushed
        }
    }
}

// ---------------------------------------------------------------------------
// Pass 3 (parallel): out = W2 @ relu(W1 @ x + b1) + b2, per timestep.
// ---------------------------------------------------------------------------
__global__ void mlp_kernel(const float* __restrict__ W1, const float* __restrict__ b1,
                           const float* __restrict__ W2, const float* __restrict__ b2,
                           const float* __restrict__ memb, float* __restrict__ out) {
    __shared__ float sW1[HID * 3];
    __shared__ float sb1[HID];
    __shared__ float sW2[3 * HID];
    __shared__ float sb2[3];

    int tid = threadIdx.x;
    for (int i = tid; i < HID * 3; i += 256) { sW1[i] = W1[i]; sW2[i] = W2[i]; }
    if (tid < HID) sb1[tid] = b1[tid];
    if (tid < 3)   sb2[tid] = b2[tid];
    __syncthreads();

    int t0 = blockIdx.x * 1024 + tid;

    float X0[4], X1[4], X2[4], Ac0[4], Ac1[4], Ac2[4];
#pragma unroll
    for (int k = 0; k < 4; k++) {
        int t = t0 + k * 256;
        X0[k] = memb[t];
        X1[k] = memb[SEQ + t];
        X2[k] = memb[2 * SEQ + t];
        Ac0[k] = sb2[0]; Ac1[k] = sb2[1]; Ac2[k] = sb2[2];
    }

#pragma unroll 8
    for (int h = 0; h < HID; h++) {
        float w0 = sW1[3 * h], w1 = sW1[3 * h + 1], w2 = sW1[3 * h + 2];
        float bb = sb1[h];
        float v0 = sW2[h], v1 = sW2[HID + h], v2 = sW2[2 * HID + h];
#pragma unroll
        for (int k = 0; k < 4; k++) {
            float hv = fmaf(w0, X0[k], fmaf(w1, X1[k], fmaf(w2, X2[k], bb)));
            hv = fmaxf(hv, 0.0f);
            Ac0[k] = fmaf(v0, hv, Ac0[k]);
            Ac1[k] = fmaf(v1, hv, Ac1[k]);
            Ac2[k] = fmaf(v2, hv, Ac2[k]);
        }
    }

#pragma unroll
    for (int k = 0; k < 4; k++) {
        int t = t0 + k * 256;
        out[t]           = Ac0[k];
        out[SEQ + t]     = Ac1[k];
        out[2 * SEQ + t] = Ac2[k];
    }
}

// ---------------------------------------------------------------------------
// Inputs (metadata order): u, dt, A, B, bA, W1, b1, W2, b2
// Output: [outputs (3*SEQ) | membranes (3*SEQ)]
// ---------------------------------------------------------------------------
extern "C" void kernel_launch(void* const* d_in, const int* in_sizes, int n_in,
                              void* d_out, int out_size) {
    const float* u  = (const float*)d_in[0];
    const float* dt = (const float*)d_in[1];
    const float* A  = (const float*)d_in[2];
    const float* B  = (const float*)d_in[3];
    const float* bA = (const float*)d_in[4];
    const float* W1 = (const float*)d_in[5];
    const float* b1 = (const float*)d_in[6];
    const float* W2 = (const float*)d_in[7];
    const float* b2 = (const float*)d_in[8];
    float* out  = (float*)d_out;
    float* memb = out + 3 * SEQ;

    prep_kernel<<<SEQ / 256, 256>>>(u, B, bA);
    scan_kernel<<<1, 128>>>(A, dt, memb);
    mlp_kernel<<<SEQ / 1024, 256>>>(W1, b1, W2, b2, memb, out);
}

// round 5
// speedup vs baseline: 44.5825x; 21.6616x over previous
#include <cuda_runtime.h>

#define SEQ 262144
#define HID 256
#define L 32                 // steps per block
#define P (SEQ / L)          // 8192 parallel blocks
#define NSWEEP 8
#define TPB_C 1024
#define BPT (P / TPB_C)      // 8 blocks per correction thread

// w transposed for coalesced lane access: wT[j*P + b] = B@u_{b*L+j} + bA
__device__ float4 g_wT[SEQ];
// block start-state guesses, plane layout s_i(b) = g_S[i*P + b]
__device__ float g_S[3 * P];
// fine-pass results: end states E_i(b) and Jacobians J_ij(b), plane layout
__device__ float g_E[3 * P];
__device__ float g_J[9 * P];

__device__ __forceinline__ float tanh_approx(float x) {
    float y; asm("tanh.approx.f32 %0, %1;" : "=f"(y) : "f"(x)); return y;
}

// ---------------------------------------------------------------------------
// Pass 1: w_t = B@u_t + bA, stored transposed; also zero the start guesses.
// ---------------------------------------------------------------------------
__global__ void prep_kernel(const float* __restrict__ u,
                            const float* __restrict__ B,
                            const float* __restrict__ bA) {
    int t = blockIdx.x * blockDim.x + threadIdx.x;
    if (t >= SEQ) return;
    if (t < 3 * P) g_S[t] = 0.0f;

    float b00 = __ldg(B + 0), b01 = __ldg(B + 1), b02 = __ldg(B + 2);
    float b10 = __ldg(B + 3), b11 = __ldg(B + 4), b12 = __ldg(B + 5);
    float b20 = __ldg(B + 6), b21 = __ldg(B + 7), b22 = __ldg(B + 8);
    float a0 = __ldg(bA + 0), a1 = __ldg(bA + 1), a2 = __ldg(bA + 2);

    float u0 = u[t], u1 = u[SEQ + t], u2 = u[2 * SEQ + t];

    float w0 = fmaf(b00, u0, fmaf(b01, u1, fmaf(b02, u2, a0)));
    float w1 = fmaf(b10, u0, fmaf(b11, u1, fmaf(b12, u2, a1)));
    float w2 = fmaf(b20, u0, fmaf(b21, u1, fmaf(b22, u2, a2)));

    int b = t / L, j = t % L;
    g_wT[j * P + b] = make_float4(w0, w1, w2, 0.0f);
}

// ---------------------------------------------------------------------------
// Fine pass: lane b runs its L steps from s_b.
//   STORE=0: accumulate exact Jacobian J_b, write (E_b, J_b).
//   STORE=1: write membrane trajectory (no Jacobian).
// Step: y = A x + w_t ; th = tanh(y) ; x += dt*th
// Jacobian: M_t = I + dt*(D ⊙rows A), J <- M_t J  =>  J_ij += dt*D_i*(A·J)_ij
// ---------------------------------------------------------------------------
template <int STORE>
__global__ void __launch_bounds__(128)
fine_kernel(const float* __restrict__ A, const float* __restrict__ dtp,
            float* __restrict__ memb) {
    int b = blockIdx.x * blockDim.x + threadIdx.x;
    if (b >= P) return;

    float dt = *dtp;
    float A00 = __ldg(A + 0), A01 = __ldg(A + 1), A02 = __ldg(A + 2);
    float A10 = __ldg(A + 3), A11 = __ldg(A + 4), A12 = __ldg(A + 5);
    float A20 = __ldg(A + 6), A21 = __ldg(A + 7), A22 = __ldg(A + 8);

    float x0 = g_S[b], x1 = g_S[P + b], x2 = g_S[2 * P + b];

    float J00 = 1.f, J01 = 0.f, J02 = 0.f;
    float J10 = 0.f, J11 = 1.f, J12 = 0.f;
    float J20 = 0.f, J21 = 0.f, J22 = 1.f;

#pragma unroll 4
    for (int j = 0; j < L; j++) {
        float4 w = g_wT[j * P + b];
        float y0 = fmaf(A00, x0, fmaf(A01, x1, fmaf(A02, x2, w.x)));
        float y1 = fmaf(A10, x0, fmaf(A11, x1, fmaf(A12, x2, w.y)));
        float y2 = fmaf(A20, x0, fmaf(A21, x1, fmaf(A22, x2, w.z)));
        float t0 = tanh_approx(y0);
        float t1 = tanh_approx(y1);
        float t2 = tanh_approx(y2);
        x0 = fmaf(dt, t0, x0);
        x1 = fmaf(dt, t1, x1);
        x2 = fmaf(dt, t2, x2);

        if (STORE) {
            int t = b * L + j;
            memb[t]           = x0;
            memb[SEQ + t]     = x1;
            memb[2 * SEQ + t] = x2;
        } else {
            float dD0 = dt * fmaf(-t0, t0, 1.0f);
            float dD1 = dt * fmaf(-t1, t1, 1.0f);
            float dD2 = dt * fmaf(-t2, t2, 1.0f);
            // T = A * J
            float T00 = fmaf(A00, J00, fmaf(A01, J10, A02 * J20));
            float T01 = fmaf(A00, J01, fmaf(A01, J11, A02 * J21));
            float T02 = fmaf(A00, J02, fmaf(A01, J12, A02 * J22));
            float T10 = fmaf(A10, J00, fmaf(A11, J10, A12 * J20));
            float T11 = fmaf(A10, J01, fmaf(A11, J11, A12 * J21));
            float T12 = fmaf(A10, J02, fmaf(A11, J12, A12 * J22));
            float T20 = fmaf(A20, J00, fmaf(A21, J10, A22 * J20));
            float T21 = fmaf(A20, J01, fmaf(A21, J11, A22 * J21));
            float T22 = fmaf(A20, J02, fmaf(A21, J12, A22 * J22));
            // J += (dt*D_i) * T  (row-scaled)
            J00 = fmaf(dD0, T00, J00); J01 = fmaf(dD0, T01, J01); J02 = fmaf(dD0, T02, J02);
            J10 = fmaf(dD1, T10, J10); J11 = fmaf(dD1, T11, J11); J12 = fmaf(dD1, T12, J12);
            J20 = fmaf(dD2, T20, J20); J21 = fmaf(dD2, T21, J21); J22 = fmaf(dD2, T22, J22);
        }
    }

    if (!STORE) {
        g_E[b] = x0; g_E[P + b] = x1; g_E[2 * P + b] = x2;
        g_J[0 * P + b] = J00; g_J[1 * P + b] = J01; g_J[2 * P + b] = J02;
        g_J[3 * P + b] = J10; g_J[4 * P + b] = J11; g_J[5 * P + b] = J12;
        g_J[6 * P + b] = J20; g_J[7 * P + b] = J21; g_J[8 * P + b] = J22;
    }
}

// ---------------------------------------------------------------------------
// Correction: exact solve of X_{b+1} = delta_b + J_b X_b, X_0 = 0,
// delta_b = E_b - J_b s_b  (s_b = OLD guess, the linearization point!).
// Parallel scan over affine (J, d) pairs; new guesses s_b <- X_b.
// Single CTA, 1024 threads, 8 blocks/thread.
// ---------------------------------------------------------------------------
struct Aff { float J[9]; float d[3]; };

__device__ __forceinline__ Aff aff_identity() {
    Aff a;
    a.J[0] = 1.f; a.J[1] = 0.f; a.J[2] = 0.f;
    a.J[3] = 0.f; a.J[4] = 1.f; a.J[5] = 0.f;
    a.J[6] = 0.f; a.J[7] = 0.f; a.J[8] = 1.f;
    a.d[0] = a.d[1] = a.d[2] = 0.f;
    return a;
}

// result = hi ∘ lo (apply lo first, then hi)
__device__ __forceinline__ Aff aff_compose(const Aff& hi, const Aff& lo) {
    Aff r;
#pragma unroll
    for (int i = 0; i < 3; i++) {
#pragma unroll
        for (int j = 0; j < 3; j++) {
            r.J[i * 3 + j] = fmaf(hi.J[i * 3 + 0], lo.J[0 * 3 + j],
                             fmaf(hi.J[i * 3 + 1], lo.J[1 * 3 + j],
                                  hi.J[i * 3 + 2] * lo.J[2 * 3 + j]));
        }
        r.d[i] = fmaf(hi.J[i * 3 + 0], lo.d[0],
                 fmaf(hi.J[i * 3 + 1], lo.d[1],
                 fmaf(hi.J[i * 3 + 2], lo.d[2], hi.d[i])));
    }
    return r;
}

__device__ __forceinline__ Aff aff_shfl_up(const Aff& a, int off) {
    Aff r;
#pragma unroll
    for (int i = 0; i < 9; i++) r.J[i] = __shfl_up_sync(0xFFFFFFFFu, a.J[i], off);
#pragma unroll
    for (int i = 0; i < 3; i++) r.d[i] = __shfl_up_sync(0xFFFFFFFFu, a.d[i], off);
    return r;
}

__device__ __forceinline__ Aff load_affine(int b) {
    Aff m;
#pragma unroll
    for (int i = 0; i < 9; i++) m.J[i] = g_J[i * P + b];
    float s0 = g_S[b], s1 = g_S[P + b], s2 = g_S[2 * P + b];
#pragma unroll
    for (int i = 0; i < 3; i++) {
        m.d[i] = g_E[i * P + b]
               - fmaf(m.J[i * 3 + 0], s0,
                 fmaf(m.J[i * 3 + 1], s1, m.J[i * 3 + 2] * s2));
    }
    return m;
}

__global__ void __launch_bounds__(TPB_C)
correct_kernel() {
    int tid  = threadIdx.x;
    int lane = tid & 31;
    int wid  = tid >> 5;
    int b0   = tid * BPT;

    // phase 1: thread-serial aggregate over its 8 blocks
    Aff acc = aff_identity();
#pragma unroll
    for (int e = 0; e < BPT; e++) acc = aff_compose(load_affine(b0 + e), acc);

    // warp-level inclusive Kogge-Stone scan
    Aff inc = acc;
#pragma unroll
    for (int off = 1; off < 32; off <<= 1) {
        Aff o = aff_shfl_up(inc, off);
        if (lane >= off) inc = aff_compose(inc, o);
    }

    __shared__ Aff warpTot[32];
    __shared__ Aff warpPre[32];
    if (lane == 31) warpTot[wid] = inc;
    __syncthreads();
    if (tid == 0) {
        Aff run = aff_identity();
        for (int w = 0; w < 32; w++) {
            warpPre[w] = run;
            run = aff_compose(warpTot[w], run);
        }
    }
    __syncthreads();

    // exclusive prefix for this thread
    Aff exc = aff_shfl_up(inc, 1);
    if (lane == 0) exc = aff_identity();
    Aff pre = aff_compose(exc, warpPre[wid]);

    // X at the start of this thread's first block (X_0 = 0 -> just d)
    float X0 = pre.d[0], X1 = pre.d[1], X2 = pre.d[2];
#pragma unroll
    for (int e = 0; e < BPT; e++) {
        int b = b0 + e;
        // CRITICAL ORDER: read affine (delta uses the OLD s_b linearization
        // point) BEFORE overwriting g_S[b] with the new guess.
        Aff m = load_affine(b);
        g_S[b] = X0; g_S[P + b] = X1; g_S[2 * P + b] = X2;
        float n0 = fmaf(m.J[0], X0, fmaf(m.J[1], X1, fmaf(m.J[2], X2, m.d[0])));
        float n1 = fmaf(m.J[3], X0, fmaf(m.J[4], X1, fmaf(m.J[5], X2, m.d[1])));
        float n2 = fmaf(m.J[6], X0, fmaf(m.J[7], X1, fmaf(m.J[8], X2, m.d[2])));
        X0 = n0; X1 = n1; X2 = n2;
    }
}

// ---------------------------------------------------------------------------
// MLP: out = W2 @ relu(W1 @ x + b1) + b2, per timestep.
// ---------------------------------------------------------------------------
__global__ void mlp_kernel(const float* __restrict__ W1, const float* __restrict__ b1,
                           const float* __restrict__ W2, const float* __restrict__ b2,
                           const float* __restrict__ memb, float* __restrict__ out) {
    __shared__ float sW1[HID * 3];
    __shared__ float sb1[HID];
    __shared__ float sW2[3 * HID];
    __shared__ float sb2[3];

    int tid = threadIdx.x;
    for (int i = tid; i < HID * 3; i += 256) { sW1[i] = W1[i]; sW2[i] = W2[i]; }
    if (tid < HID) sb1[tid] = b1[tid];
    if (tid < 3)   sb2[tid] = b2[tid];
    __syncthreads();

    int t0 = blockIdx.x * 1024 + tid;

    float X0[4], X1[4], X2[4], Ac0[4], Ac1[4], Ac2[4];
#pragma unroll
    for (int k = 0; k < 4; k++) {
        int t = t0 + k * 256;
        X0[k] = memb[t];
        X1[k] = memb[SEQ + t];
        X2[k] = memb[2 * SEQ + t];
        Ac0[k] = sb2[0]; Ac1[k] = sb2[1]; Ac2[k] = sb2[2];
    }

#pragma unroll 8
    for (int h = 0; h < HID; h++) {
        float w0 = sW1[3 * h], w1 = sW1[3 * h + 1], w2 = sW1[3 * h + 2];
        float bb = sb1[h];
        float v0 = sW2[h], v1 = sW2[HID + h], v2 = sW2[2 * HID + h];
#pragma unroll
        for (int k = 0; k < 4; k++) {
            float hv = fmaf(w0, X0[k], fmaf(w1, X1[k], fmaf(w2, X2[k], bb)));
            hv = fmaxf(hv, 0.0f);
            Ac0[k] = fmaf(v0, hv, Ac0[k]);
            Ac1[k] = fmaf(v1, hv, Ac1[k]);
            Ac2[k] = fmaf(v2, hv, Ac2[k]);
        }
    }

#pragma unroll
    for (int k = 0; k < 4; k++) {
        int t = t0 + k * 256;
        out[t]           = Ac0[k];
        out[SEQ + t]     = Ac1[k];
        out[2 * SEQ + t] = Ac2[k];
    }
}

// ---------------------------------------------------------------------------
// Inputs (metadata order): u, dt, A, B, bA, W1, b1, W2, b2
// Output: [outputs (3*SEQ) | membranes (3*SEQ)]
// ---------------------------------------------------------------------------
extern "C" void kernel_launch(void* const* d_in, const int* in_sizes, int n_in,
                              void* d_out, int out_size) {
    const float* u  = (const float*)d_in[0];
    const float* dt = (const float*)d_in[1];
    const float* A  = (const float*)d_in[2];
    const float* B  = (const float*)d_in[3];
    const float* bA = (const float*)d_in[4];
    const float* W1 = (const float*)d_in[5];
    const float* b1 = (const float*)d_in[6];
    const float* W2 = (const float*)d_in[7];
    const float* b2 = (const float*)d_in[8];
    float* out  = (float*)d_out;
    float* memb = out + 3 * SEQ;

    prep_kernel<<<SEQ / 256, 256>>>(u, B, bA);
    for (int k = 0; k < NSWEEP; k++) {
        fine_kernel<0><<<P / 128, 128>>>(A, dt, memb);
        correct_kernel<<<1, TPB_C>>>();
    }
    fine_kernel<1><<<P / 128, 128>>>(A, dt, memb);
    mlp_kernel<<<SEQ / 1024, 256>>>(W1, b1, W2, b2, memb, out);
}

// round 6
// speedup vs baseline: 172.6347x; 3.8723x over previous
#include <cuda_runtime.h>

#define SEQ 262144
#define HID 256
#define L 32                  // steps per block (one block per thread)
#define P (SEQ / L)           // 8192 threads total
#define TPB 64
#define GRID (P / TPB)        // 128 CTAs (<148 SMs -> all resident, spin barrier safe)
#define NSWEEP 5

// w transposed for coalesced per-sweep reads: wT[j*P + b] = B@u_{b*L+j} + bA
__device__ float4 g_wT[SEQ];

// inter-CTA exchange: per-sweep CTA-total affines (double buffered)
struct Aff { float J[9]; float d[3]; };
__device__ Aff g_ctaTot[2][GRID];

// grid barrier state: counters reset by last arriver; flags monotone
__device__ unsigned g_cnt[NSWEEP];
__device__ volatile unsigned g_flag[NSWEEP];

__device__ __forceinline__ float tanh_approx(float x) {
    float y; asm("tanh.approx.f32 %0, %1;" : "=f"(y) : "f"(x)); return y;
}

__device__ __forceinline__ Aff aff_identity() {
    Aff a;
    a.J[0] = 1.f; a.J[1] = 0.f; a.J[2] = 0.f;
    a.J[3] = 0.f; a.J[4] = 1.f; a.J[5] = 0.f;
    a.J[6] = 0.f; a.J[7] = 0.f; a.J[8] = 1.f;
    a.d[0] = a.d[1] = a.d[2] = 0.f;
    return a;
}

// result = hi ∘ lo (lo applied first)
__device__ __forceinline__ Aff aff_compose(const Aff& hi, const Aff& lo) {
    Aff r;
#pragma unroll
    for (int i = 0; i < 3; i++) {
#pragma unroll
        for (int j = 0; j < 3; j++) {
            r.J[i * 3 + j] = fmaf(hi.J[i * 3 + 0], lo.J[0 * 3 + j],
                             fmaf(hi.J[i * 3 + 1], lo.J[1 * 3 + j],
                                  hi.J[i * 3 + 2] * lo.J[2 * 3 + j]));
        }
        r.d[i] = fmaf(hi.J[i * 3 + 0], lo.d[0],
                 fmaf(hi.J[i * 3 + 1], lo.d[1],
                 fmaf(hi.J[i * 3 + 2], lo.d[2], hi.d[i])));
    }
    return r;
}

__device__ __forceinline__ Aff aff_shfl_up(const Aff& a, int off) {
    Aff r;
#pragma unroll
    for (int i = 0; i < 9; i++) r.J[i] = __shfl_up_sync(0xFFFFFFFFu, a.J[i], off);
#pragma unroll
    for (int i = 0; i < 3; i++) r.d[i] = __shfl_up_sync(0xFFFFFFFFu, a.d[i], off);
    return r;
}

// Grid-wide barrier, instance i (each instance used once per kernel run).
// Release flag is read BEFORE arriving: it cannot advance until this CTA
// arrives, so the pre-read is race-free. Last arriver resets the counter
// (leaves clean state for the next graph replay) and bumps the flag.
__device__ __forceinline__ void grid_barrier(int i) {
    __syncthreads();
    if (threadIdx.x == 0) {
        __threadfence();
        unsigned old = g_flag[i];
        unsigned n = atomicAdd(&g_cnt[i], 1u);
        if (n == GRID - 1) {
            g_cnt[i] = 0;
            __threadfence();
            g_flag[i] = old + 1u;
        } else {
            while (g_flag[i] == old) {}
        }
        __threadfence();
    }
    __syncthreads();
}

// ---------------------------------------------------------------------------
// Fused solver: prep + NSWEEP Newton-parareal sweeps + trajectory store.
// Thread b owns timestep block [b*L, (b+1)*L); its start-state guess s lives
// in registers for the whole kernel.
// ---------------------------------------------------------------------------
__global__ void __launch_bounds__(TPB, 1)
solver_kernel(const float* __restrict__ u,
              const float* __restrict__ dtp,
              const float* __restrict__ Ain,
              const float* __restrict__ Bin,
              const float* __restrict__ bAin,
              float* __restrict__ memb) {
    int tid  = threadIdx.x;
    int lane = tid & 31;
    int wid  = tid >> 5;
    int b    = blockIdx.x * TPB + tid;

    __shared__ Aff  sW0tot;
    __shared__ float sV[3];

    float dt = *dtp;
    float A00 = __ldg(Ain + 0), A01 = __ldg(Ain + 1), A02 = __ldg(Ain + 2);
    float A10 = __ldg(Ain + 3), A11 = __ldg(Ain + 4), A12 = __ldg(Ain + 5);
    float A20 = __ldg(Ain + 6), A21 = __ldg(Ain + 7), A22 = __ldg(Ain + 8);

    // ---- prep: w for this thread's own block (self-read later, no barrier) ----
    {
        float b00 = __ldg(Bin + 0), b01 = __ldg(Bin + 1), b02 = __ldg(Bin + 2);
        float b10 = __ldg(Bin + 3), b11 = __ldg(Bin + 4), b12 = __ldg(Bin + 5);
        float b20 = __ldg(Bin + 6), b21 = __ldg(Bin + 7), b22 = __ldg(Bin + 8);
        float a0 = __ldg(bAin + 0), a1 = __ldg(bAin + 1), a2 = __ldg(bAin + 2);
        int t0 = b * L;
#pragma unroll 4
        for (int j = 0; j < L; j++) {
            float u0 = u[t0 + j], u1 = u[SEQ + t0 + j], u2 = u[2 * SEQ + t0 + j];
            float w0 = fmaf(b00, u0, fmaf(b01, u1, fmaf(b02, u2, a0)));
            float w1 = fmaf(b10, u0, fmaf(b11, u1, fmaf(b12, u2, a1)));
            float w2 = fmaf(b20, u0, fmaf(b21, u1, fmaf(b22, u2, a2)));
            g_wT[j * P + b] = make_float4(w0, w1, w2, 0.0f);
        }
    }

    float s0 = 0.f, s1 = 0.f, s2 = 0.f;   // start-state guess (registers!)

    for (int sweep = 0; sweep < NSWEEP; sweep++) {
        // ---- fine pass with exact Jacobian (all registers) ----
        float x0 = s0, x1 = s1, x2 = s2;
        float J00 = 1.f, J01 = 0.f, J02 = 0.f;
        float J10 = 0.f, J11 = 1.f, J12 = 0.f;
        float J20 = 0.f, J21 = 0.f, J22 = 1.f;
#pragma unroll 4
        for (int j = 0; j < L; j++) {
            float4 w = g_wT[j * P + b];
            float y0 = fmaf(A00, x0, fmaf(A01, x1, fmaf(A02, x2, w.x)));
            float y1 = fmaf(A10, x0, fmaf(A11, x1, fmaf(A12, x2, w.y)));
            float y2 = fmaf(A20, x0, fmaf(A21, x1, fmaf(A22, x2, w.z)));
            float t0 = tanh_approx(y0);
            float t1 = tanh_approx(y1);
            float t2 = tanh_approx(y2);
            x0 = fmaf(dt, t0, x0);
            x1 = fmaf(dt, t1, x1);
            x2 = fmaf(dt, t2, x2);
            float dD0 = dt * fmaf(-t0, t0, 1.0f);
            float dD1 = dt * fmaf(-t1, t1, 1.0f);
            float dD2 = dt * fmaf(-t2, t2, 1.0f);
            float T00 = fmaf(A00, J00, fmaf(A01, J10, A02 * J20));
            float T01 = fmaf(A00, J01, fmaf(A01, J11, A02 * J21));
            float T02 = fmaf(A00, J02, fmaf(A01, J12, A02 * J22));
            float T10 = fmaf(A10, J00, fmaf(A11, J10, A12 * J20));
            float T11 = fmaf(A10, J01, fmaf(A11, J11, A12 * J21));
            float T12 = fmaf(A10, J02, fmaf(A11, J12, A12 * J22));
            float T20 = fmaf(A20, J00, fmaf(A21, J10, A22 * J20));
            float T21 = fmaf(A20, J01, fmaf(A21, J11, A22 * J21));
            float T22 = fmaf(A20, J02, fmaf(A21, J12, A22 * J22));
            J00 = fmaf(dD0, T00, J00); J01 = fmaf(dD0, T01, J01); J02 = fmaf(dD0, T02, J02);
            J10 = fmaf(dD1, T10, J10); J11 = fmaf(dD1, T11, J11); J12 = fmaf(dD1, T12, J12);
            J20 = fmaf(dD2, T20, J20); J21 = fmaf(dD2, T21, J21); J22 = fmaf(dD2, T22, J22);
        }

        // ---- affine map for this block: X_next = J X + (E - J s) ----
        Aff m;
        m.J[0] = J00; m.J[1] = J01; m.J[2] = J02;
        m.J[3] = J10; m.J[4] = J11; m.J[5] = J12;
        m.J[6] = J20; m.J[7] = J21; m.J[8] = J22;
        m.d[0] = x0 - fmaf(J00, s0, fmaf(J01, s1, J02 * s2));
        m.d[1] = x1 - fmaf(J10, s0, fmaf(J11, s1, J12 * s2));
        m.d[2] = x2 - fmaf(J20, s0, fmaf(J21, s1, J22 * s2));

        // ---- warp inclusive Kogge-Stone scan ----
        Aff inc = m;
#pragma unroll
        for (int off = 1; off < 32; off <<= 1) {
            Aff o = aff_shfl_up(inc, off);
            if (lane >= off) inc = aff_compose(inc, o);
        }

        // ---- CTA combine (2 warps) ----
        if (wid == 0 && lane == 31) sW0tot = inc;
        __syncthreads();
        Aff exc = aff_shfl_up(inc, 1);
        if (lane == 0) exc = aff_identity();
        if (wid == 1) exc = aff_compose(exc, sW0tot);   // CTA-exclusive affine

        // ---- publish CTA total, grid barrier ----
        int buf = sweep & 1;
        if (tid == TPB - 1) {
            Aff tot = aff_compose(inc, sW0tot);
            g_ctaTot[buf][blockIdx.x] = tot;
            __threadfence();
        }
        grid_barrier(sweep);

        // ---- thread 0: propagate V through preceding CTA totals ----
        if (tid == 0) {
            float V0 = 0.f, V1 = 0.f, V2 = 0.f;
            for (int c = 0; c < blockIdx.x; c++) {
                Aff T = g_ctaTot[buf][c];
                float n0 = fmaf(T.J[0], V0, fmaf(T.J[1], V1, fmaf(T.J[2], V2, T.d[0])));
                float n1 = fmaf(T.J[3], V0, fmaf(T.J[4], V1, fmaf(T.J[5], V2, T.d[1])));
                float n2 = fmaf(T.J[6], V0, fmaf(T.J[7], V1, fmaf(T.J[8], V2, T.d[2])));
                V0 = n0; V1 = n1; V2 = n2;
            }
            sV[0] = V0; sV[1] = V1; sV[2] = V2;
        }
        __syncthreads();

        // ---- Newton update of this thread's start guess ----
        float V0 = sV[0], V1 = sV[1], V2 = sV[2];
        s0 = fmaf(exc.J[0], V0, fmaf(exc.J[1], V1, fmaf(exc.J[2], V2, exc.d[0])));
        s1 = fmaf(exc.J[3], V0, fmaf(exc.J[4], V1, fmaf(exc.J[5], V2, exc.d[1])));
        s2 = fmaf(exc.J[6], V0, fmaf(exc.J[7], V1, fmaf(exc.J[8], V2, exc.d[2])));
        __syncthreads();
    }

    // ---- final trajectory store (no Jacobian) ----
    {
        float x0 = s0, x1 = s1, x2 = s2;
        int t0 = b * L;
#pragma unroll 4
        for (int j = 0; j < L; j++) {
            float4 w = g_wT[j * P + b];
            float y0 = fmaf(A00, x0, fmaf(A01, x1, fmaf(A02, x2, w.x)));
            float y1 = fmaf(A10, x0, fmaf(A11, x1, fmaf(A12, x2, w.y)));
            float y2 = fmaf(A20, x0, fmaf(A21, x1, fmaf(A22, x2, w.z)));
            x0 = fmaf(dt, tanh_approx(y0), x0);
            x1 = fmaf(dt, tanh_approx(y1), x1);
            x2 = fmaf(dt, tanh_approx(y2), x2);
            memb[t0 + j]           = x0;
            memb[SEQ + t0 + j]     = x1;
            memb[2 * SEQ + t0 + j] = x2;
        }
    }
}

// ---------------------------------------------------------------------------
// MLP: out = W2 @ relu(W1 @ x + b1) + b2, per timestep.
// ---------------------------------------------------------------------------
__global__ void mlp_kernel(const float* __restrict__ W1, const float* __restrict__ b1,
                           const float* __restrict__ W2, const float* __restrict__ b2,
                           const float* __restrict__ memb, float* __restrict__ out) {
    __shared__ float sW1[HID * 3];
    __shared__ float sb1[HID];
    __shared__ float sW2[3 * HID];
    __shared__ float sb2[3];

    int tid = threadIdx.x;
    for (int i = tid; i < HID * 3; i += 256) { sW1[i] = W1[i]; sW2[i] = W2[i]; }
    if (tid < HID) sb1[tid] = b1[tid];
    if (tid < 3)   sb2[tid] = b2[tid];
    __syncthreads();

    int t0 = blockIdx.x * 1024 + tid;

    float X0[4], X1[4], X2[4], Ac0[4], Ac1[4], Ac2[4];
#pragma unroll
    for (int k = 0; k < 4; k++) {
        int t = t0 + k * 256;
        X0[k] = memb[t];
        X1[k] = memb[SEQ + t];
        X2[k] = memb[2 * SEQ + t];
        Ac0[k] = sb2[0]; Ac1[k] = sb2[1]; Ac2[k] = sb2[2];
    }

#pragma unroll 8
    for (int h = 0; h < HID; h++) {
        float w0 = sW1[3 * h], w1 = sW1[3 * h + 1], w2 = sW1[3 * h + 2];
        float bb = sb1[h];
        float v0 = sW2[h], v1 = sW2[HID + h], v2 = sW2[2 * HID + h];
#pragma unroll
        for (int k = 0; k < 4; k++) {
            float hv = fmaf(w0, X0[k], fmaf(w1, X1[k], fmaf(w2, X2[k], bb)));
            hv = fmaxf(hv, 0.0f);
            Ac0[k] = fmaf(v0, hv, Ac0[k]);
            Ac1[k] = fmaf(v1, hv, Ac1[k]);
            Ac2[k] = fmaf(v2, hv, Ac2[k]);
        }
    }

#pragma unroll
    for (int k = 0; k < 4; k++) {
        int t = t0 + k * 256;
        out[t]           = Ac0[k];
        out[SEQ + t]     = Ac1[k];
        out[2 * SEQ + t] = Ac2[k];
    }
}

// ---------------------------------------------------------------------------
// Inputs (metadata order): u, dt, A, B, bA, W1, b1, W2, b2
// Output: [outputs (3*SEQ) | membranes (3*SEQ)]
// ---------------------------------------------------------------------------
extern "C" void kernel_launch(void* const* d_in, const int* in_sizes, int n_in,
                              void* d_out, int out_size) {
    const float* u  = (const float*)d_in[0];
    const float* dt = (const float*)d_in[1];
    const float* A  = (const float*)d_in[2];
    const float* B  = (const float*)d_in[3];
    const float* bA = (const float*)d_in[4];
    const float* W1 = (const float*)d_in[5];
    const float* b1 = (const float*)d_in[6];
    const float* W2 = (const float*)d_in[7];
    const float* b2 = (const float*)d_in[8];
    float* out  = (float*)d_out;
    float* memb = out + 3 * SEQ;

    solver_kernel<<<GRID, TPB>>>(u, dt, A, B, bA, memb);
    mlp_kernel<<<SEQ / 1024, 256>>>(W1, b1, W2, b2, memb, out);
}